// round 14
// baseline (speedup 1.0000x reference)
#include <cuda_runtime.h>

#define SCALE 0.17677669529663687f
#define NTHR  256

// u32-word smem offsets — per-CTA smem = 97,792 B (2 CTAs/SM)
// XHH [0,3808)   : hi plane, 56 rows x 68 words (stride 272B, LDSM-clean)
// XHL [3808,7616): lo plane
// KH  [7616,15232): uint2 56x68 (hi,lo packed) — B operand for QK
// VT  [15232,24448): uint2 128x36 — B operand for AV
// OV planes overlay XH planes (q dead per-region as tasks complete)
#define SM_U2 12224

__device__ uint4  gW4[64 * 8 * 8 * 4];      // fragment-major pre-split weights
__device__ float2 gBM[64 * 4 * 7 * 49 * 4]; // bias+mask: [wm][h][jb][li][t]

__device__ __forceinline__ unsigned pack_bf(float x0, float x1) {
    unsigned r;
    asm("cvt.rn.bf16x2.f32 %0, %1, %2;" : "=r"(r) : "f"(x1), "f"(x0));
    return r;
}
__device__ __forceinline__ uint2 split_pack(float x0, float x1) {
    unsigned h = pack_bf(x0, x1);
    float h0 = __uint_as_float(h << 16);
    float h1 = __uint_as_float(h & 0xffff0000u);
    unsigned l = pack_bf(x0 - h0, x1 - h1);
    return make_uint2(h, l);
}
__device__ __forceinline__ void mmabf(float* d, const unsigned* a, const unsigned* b) {
    asm volatile("mma.sync.aligned.m16n8k16.row.col.f32.bf16.bf16.f32 "
        "{%0,%1,%2,%3},{%4,%5,%6,%7},{%8,%9},{%0,%1,%2,%3};"
        : "+f"(d[0]), "+f"(d[1]), "+f"(d[2]), "+f"(d[3])
        : "r"(a[0]), "r"(a[1]), "r"(a[2]), "r"(a[3]), "r"(b[0]), "r"(b[1]));
}
__device__ __forceinline__ void mma3(float* d, const unsigned ah[4], const unsigned al[4],
                                     uint2 b0, uint2 b1) {
    unsigned bh[2] = {b0.x, b1.x};
    unsigned bl[2] = {b0.y, b1.y};
    mmabf(d, ah, bl);
    mmabf(d, al, bh);
    mmabf(d, ah, bh);
}
__device__ __forceinline__ void ldsm4(unsigned r[4], unsigned a) {
    asm volatile("ldmatrix.sync.aligned.m8n8.x4.shared.b16 {%0,%1,%2,%3}, [%4];"
        : "=r"(r[0]), "=r"(r[1]), "=r"(r[2]), "=r"(r[3]) : "r"(a));
}

// Dense stage: warp computes 32 rows (two 16-row subtiles) x 32 cols, K=128.
__device__ __forceinline__ void mma_dense_ldsm(unsigned hb, unsigned lb,
                                               const uint4* __restrict__ gBw,
                                               float d[2][4][4], int lane)
{
    #pragma unroll
    for (int kb = 0; kb < 8; ++kb) {
        unsigned ah0[4], al0[4], ah1[4], al1[4];
        ldsm4(ah0, hb + kb * 32);
        ldsm4(al0, lb + kb * 32);
        ldsm4(ah1, hb + 4352 + kb * 32);     // +16 rows * 272B
        ldsm4(al1, lb + 4352 + kb * 32);
        #pragma unroll
        for (int nb = 0; nb < 4; ++nb) {
            uint4 f = gBw[nb * 256 + kb * 32 + lane];   // 512B coalesced
            uint2 b0 = make_uint2(f.x, f.y);
            uint2 b1 = make_uint2(f.z, f.w);
            mma3(d[0][nb], ah0, al0, b0, b1);
            mma3(d[1][nb], ah1, al1, b0, b1);
        }
    }
}

// combined prep: blocks [0,64) build gW4, blocks [64,..) build gBM
__global__ void prep_all(const float* __restrict__ qkv_w,
                         const float* __restrict__ proj_w,
                         const float* __restrict__ attn_mask,
                         const float* __restrict__ bias_table,
                         const int*   __restrict__ rel_idx)
{
    if (blockIdx.x < 64) {
        int idx = blockIdx.x * 256 + threadIdx.x;       // 0..16383
        int t    = idx & 3;
        int g    = (idx >> 2) & 7;
        int kb   = (idx >> 5) & 7;
        int cblk = idx >> 8;
        int col  = cblk * 8 + g;
        const float* src = (col < 384) ? (qkv_w + (size_t)col * 128)
                                       : (proj_w + (size_t)(col - 384) * 128);
        int w0 = kb * 8 + t, w1 = w0 + 4;
        uint2 p0 = split_pack(src[2 * w0], src[2 * w0 + 1]);
        uint2 p1 = split_pack(src[2 * w1], src[2 * w1 + 1]);
        gW4[idx] = make_uint4(p0.x, p0.y, p1.x, p1.y);
    } else {
        int idx = (blockIdx.x - 64) * 256 + threadIdx.x;
        if (idx >= 64 * 4 * 7 * 49 * 4) return;
        int t  = idx & 3;
        int q  = idx >> 2;
        int li = q % 49;   q /= 49;
        int jb = q % 7;    q /= 7;
        int h  = q & 3;
        int wm = q >> 2;
        int j0 = jb * 8 + 2 * t;
        float v0 = -1e30f, v1 = -1e30f;
        if (j0 < 49)
            v0 = bias_table[rel_idx[li * 49 + j0] * 4 + h] + attn_mask[wm * 2401 + li * 49 + j0];
        if (j0 + 1 < 49)
            v1 = bias_table[rel_idx[li * 49 + j0 + 1] * 4 + h] + attn_mask[wm * 2401 + li * 49 + j0 + 1];
        gBM[idx] = make_float2(v0, v1);
    }
}

__global__ __launch_bounds__(NTHR, 2)
void wmsa_fused_kernel(const float* __restrict__ x,
                       const float* __restrict__ qkv_b,
                       const float* __restrict__ proj_b,
                       float* __restrict__ out)
{
    extern __shared__ unsigned sm32[];
    unsigned* XHH = sm32;                    // hi plane (x -> q -> ov)
    unsigned* XHL = sm32 + 3808;             // lo plane
    uint2*    KH  = (uint2*)(sm32 + 7616);
    uint2*    VT  = (uint2*)(sm32 + 15232);

    const int tid  = threadIdx.x;
    const int bx   = blockIdx.x;
    const int lane = tid & 31;
    const int wid  = tid >> 5;               // 0..7
    const int g    = lane >> 2;
    const int t    = lane & 3;

    const int mt2   = wid >> 2;              // 0..1
    const int nh    = wid & 3;
    const int rbase = mt2 * 32;
    const int cb    = nh * 32;
    const uint4* gBq = gW4 + (cb >> 3) * 256;

    const unsigned sb = (unsigned)__cvta_generic_to_shared(sm32);
    const unsigned rowoff = (lane & 15) * 272 + (lane >> 4) * 16;  // canonical LDSM addr
    const unsigned xhh_b = sb + rowoff;
    const unsigned xhl_b = sb + 3808u * 4 + rowoff;

    // ---------------- phase 0: load+split x (planes) ; zero VT + KH pads ----------------
    {
        const float2* xg = (const float2*)(x + (size_t)bx * 49 * 128);
        for (int idx = tid; idx < 49 * 64; idx += NTHR) {
            float2 v = xg[idx];
            uint2 p = split_pack(v.x, v.y);
            int o = (idx >> 6) * 68 + (idx & 63);
            XHH[o] = p.x;
            XHL[o] = p.y;
        }
        for (int idx = tid; idx < 128 * 36; idx += NTHR)
            VT[idx] = make_uint2(0, 0);
        for (int idx = tid; idx < 7 * 68; idx += NTHR)      // KH rows 49..55 = 0
            KH[49 * 68 + idx] = make_uint2(0, 0);
    }
    __syncthreads();

    // ---------------- phase 1: K, V, Q ----------------
    {   // K (col block 16)
        float d[2][4][4] = {};
        mma_dense_ldsm(xhh_b + rbase * 272, xhl_b + rbase * 272, gBq + 16 * 256, d, lane);
        #pragma unroll
        for (int sub = 0; sub < 2; ++sub) {
            int r0 = rbase + sub * 16 + g, r1 = r0 + 8;
            #pragma unroll
            for (int nb = 0; nb < 4; ++nb) {
                int c = cb + nb * 8 + 2 * t;
                float b0 = qkv_b[128 + c], b1 = qkv_b[129 + c];
                int wcol = c >> 1;
                if (r0 < 49) KH[r0 * 68 + wcol] = split_pack(d[sub][nb][0] + b0, d[sub][nb][1] + b1);
                if (r1 < 49) KH[r1 * 68 + wcol] = split_pack(d[sub][nb][2] + b0, d[sub][nb][3] + b1);
            }
        }
    }
    {   // V (col block 32) -> VT transposed via shfl pairing
        float d[2][4][4] = {};
        mma_dense_ldsm(xhh_b + rbase * 272, xhl_b + rbase * 272, gBq + 32 * 256, d, lane);
        #pragma unroll
        for (int sub = 0; sub < 2; ++sub) {
            #pragma unroll
            for (int nb = 0; nb < 4; ++nb) {
                int c = cb + nb * 8 + 2 * t;
                float b0 = qkv_b[256 + c], b1 = qkv_b[257 + c];
                #pragma unroll
                for (int rr = 0; rr < 2; ++rr) {
                    float vc  = d[sub][nb][2 * rr]     + b0;
                    float vc1 = d[sub][nb][2 * rr + 1] + b1;
                    float oc  = __shfl_xor_sync(0xffffffffu, vc, 4);
                    float oc1 = __shfl_xor_sync(0xffffffffu, vc1, 4);
                    int il = rbase + sub * 16 + rr * 8 + g;
                    if (!(g & 1) && il < 49) {
                        float e1 = (il + 1 < 49) ? oc  : 0.f;
                        float f1 = (il + 1 < 49) ? oc1 : 0.f;
                        int u = il >> 1;
                        VT[c * 36 + u]       = split_pack(vc,  e1);
                        VT[(c + 1) * 36 + u] = split_pack(vc1, f1);
                    }
                }
            }
        }
    }
    {   // Q (col block 0): compute, sync, overwrite XH planes
        float d[2][4][4] = {};
        mma_dense_ldsm(xhh_b + rbase * 272, xhl_b + rbase * 272, gBq, d, lane);
        __syncthreads();                      // all XH reads done
        #pragma unroll
        for (int sub = 0; sub < 2; ++sub) {
            int r0 = rbase + sub * 16 + g, r1 = r0 + 8;
            #pragma unroll
            for (int nb = 0; nb < 4; ++nb) {
                int c = cb + nb * 8 + 2 * t;
                float b0 = qkv_b[c], b1 = qkv_b[c + 1];
                int wcol = c >> 1;
                if (r0 < 49) {
                    uint2 p = split_pack((d[sub][nb][0] + b0) * SCALE, (d[sub][nb][1] + b1) * SCALE);
                    XHH[r0 * 68 + wcol] = p.x;
                    XHL[r0 * 68 + wcol] = p.y;
                }
                if (r1 < 49) {
                    uint2 p = split_pack((d[sub][nb][2] + b0) * SCALE, (d[sub][nb][3] + b1) * SCALE);
                    XHH[r1 * 68 + wcol] = p.x;
                    XHL[r1 * 68 + wcol] = p.y;
                }
            }
        }
    }
    __syncthreads();

    // ------- phases 2-4 fused: per-task QK -> softmax -> AV -> inline OV store -------
    // OV overlays the q planes. Safe: task (h,qt) writes words [16h,16h+16) of rows
    // qt*16..qt*16+15; concurrent QK readers with same h have different qt (disjoint
    // rows), readers with different h touch disjoint word ranges. VT/KH untouched.
    #pragma unroll
    for (int it = 0; it < 2; ++it) {
        int task = wid + 8 * it;              // 0..15
        int h = task >> 2, qt = task & 3;
        int row0 = qt * 16;

        // --- QK^T (A = q rows via LDSM, B = KH) ---
        float dq[7][4];
        #pragma unroll
        for (int jb = 0; jb < 7; ++jb)
            #pragma unroll
            for (int e = 0; e < 4; ++e) dq[jb][e] = 0.f;
        #pragma unroll
        for (int kb2 = 0; kb2 < 2; ++kb2) {
            int kb = 2 * h + kb2;
            unsigned ah[4], al[4];
            ldsm4(ah, xhh_b + row0 * 272 + kb * 32);
            ldsm4(al, xhl_b + row0 * 272 + kb * 32);
            int kw = kb * 8 + t;
            #pragma unroll
            for (int jb = 0; jb < 7; ++jb) {
                int kr = jb * 8 + g;
                mma3(dq[jb], ah, al, KH[kr * 68 + kw], KH[kr * 68 + kw + 4]);
            }
        }

        // --- bias+mask + softmax -> packed A fragments (regs, no smem) ---
        uint2 pa[7], pb[7];                   // rows g / g+8, per jb: (hi,lo) of col pair
        const float2* bmh = gBM + ((size_t)(bx & 63) * 4 + h) * (7 * 49 * 4);
        #pragma unroll
        for (int rr = 0; rr < 2; ++rr) {
            int li = row0 + rr * 8 + g;
            int lic = min(li, 48);
            float sv[14];
            float mx = -INFINITY;
            #pragma unroll
            for (int jb = 0; jb < 7; ++jb) {
                float2 bm = bmh[(jb * 49 + lic) * 4 + t];
                float v0 = dq[jb][rr * 2]     + bm.x;
                float v1 = dq[jb][rr * 2 + 1] + bm.y;
                sv[2 * jb]     = v0;
                sv[2 * jb + 1] = v1;
                mx = fmaxf(mx, fmaxf(v0, v1));
            }
            mx = fmaxf(mx, __shfl_xor_sync(0xffffffffu, mx, 1));
            mx = fmaxf(mx, __shfl_xor_sync(0xffffffffu, mx, 2));
            float sum = 0.f;
            #pragma unroll
            for (int n = 0; n < 14; ++n) { sv[n] = __expf(sv[n] - mx); sum += sv[n]; }
            sum += __shfl_xor_sync(0xffffffffu, sum, 1);
            sum += __shfl_xor_sync(0xffffffffu, sum, 2);
            float inv = 1.f / sum;
            uint2* dst = rr ? pb : pa;
            #pragma unroll
            for (int jb = 0; jb < 7; ++jb)
                dst[jb] = split_pack(sv[2 * jb] * inv, sv[2 * jb + 1] * inv);
        }

        // --- AV (A = packed probs from regs, B = VT) ---
        float dv[4][4] = {};
        #pragma unroll
        for (int kb = 0; kb < 4; ++kb) {
            const int jb0 = 2 * kb, jb1 = 2 * kb + 1;
            unsigned ah[4], al[4];
            ah[0] = pa[jb0].x;  al[0] = pa[jb0].y;
            ah[1] = pb[jb0].x;  al[1] = pb[jb0].y;
            if (jb1 < 7) {
                ah[2] = pa[jb1].x;  al[2] = pa[jb1].y;
                ah[3] = pb[jb1].x;  al[3] = pb[jb1].y;
            } else {
                ah[2] = 0; al[2] = 0; ah[3] = 0; al[3] = 0;
            }
            int kw = kb * 8 + t;
            #pragma unroll
            for (int nb = 0; nb < 4; ++nb) {
                int c = 32 * h + nb * 8 + g;
                mma3(dv[nb], ah, al, VT[c * 36 + kw], VT[c * 36 + kw + 4]);
            }
        }

        // --- inline OV store into the q planes (race-free, see proof above) ---
        {
            int l0 = row0 + g;
            #pragma unroll
            for (int nb = 0; nb < 4; ++nb) {
                int cw = 16 * h + nb * 4 + t;
                if (l0 < 49) {
                    uint2 p = split_pack(dv[nb][0], dv[nb][1]);
                    XHH[l0 * 68 + cw] = p.x;
                    XHL[l0 * 68 + cw] = p.y;
                }
                if (l0 + 8 < 49) {
                    uint2 p = split_pack(dv[nb][2], dv[nb][3]);
                    XHH[(l0 + 8) * 68 + cw] = p.x;
                    XHL[(l0 + 8) * 68 + cw] = p.y;
                }
            }
        }
    }
    __syncthreads();                          // all OV writes visible

    // ---------------- phase 5: proj GEMM (col block 48), A = OV in XH planes ----------------
    {
        float d[2][4][4] = {};
        mma_dense_ldsm(xhh_b + rbase * 272, xhl_b + rbase * 272, gBq + 48 * 256, d, lane);
        float* og = out + (size_t)bx * 49 * 128;
        #pragma unroll
        for (int sub = 0; sub < 2; ++sub) {
            int r0 = rbase + sub * 16 + g, r1 = r0 + 8;
            #pragma unroll
            for (int nb = 0; nb < 4; ++nb) {
                int c = cb + nb * 8 + 2 * t;
                float b0 = proj_b[c], b1 = proj_b[c + 1];
                if (r0 < 49)
                    *(float2*)(og + r0 * 128 + c) = make_float2(d[sub][nb][0] + b0, d[sub][nb][1] + b1);
                if (r1 < 49)
                    *(float2*)(og + r1 * 128 + c) = make_float2(d[sub][nb][2] + b0, d[sub][nb][3] + b1);
            }
        }
    }
}

extern "C" void kernel_launch(void* const* d_in, const int* in_sizes, int n_in,
                              void* d_out, int out_size)
{
    const float* x          = (const float*)d_in[0];
    const float* attn_mask  = (const float*)d_in[1];
    const float* qkv_w      = (const float*)d_in[2];
    const float* qkv_b      = (const float*)d_in[3];
    const float* proj_w     = (const float*)d_in[4];
    const float* proj_b     = (const float*)d_in[5];
    const float* bias_table = (const float*)d_in[6];
    const int*   rel_idx    = (const int*)d_in[7];
    float* out = (float*)d_out;

    const int bm_blocks = (64 * 4 * 7 * 49 * 4 + 255) / 256;   // 215
    prep_all<<<64 + bm_blocks, 256>>>(qkv_w, proj_w, attn_mask, bias_table, rel_idx);

    const int smem_bytes = SM_U2 * 8;                          // 97,792 B -> 2 CTAs/SM
    cudaFuncSetAttribute(wmsa_fused_kernel,
                         cudaFuncAttributeMaxDynamicSharedMemorySize, smem_bytes);

    const int n_windows = in_sizes[0] / (49 * 128);            // 4096
    wmsa_fused_kernel<<<n_windows, NTHR, smem_bytes>>>(x, qkv_b, proj_b, out);
}